// round 16
// baseline (speedup 1.0000x reference)
#include <cuda_runtime.h>
#include <cstdint>

// Problem shape (fixed per metadata): F_S [16, 64, 256, 256] float32
#define B_   16
#define C_   64
#define HW_  65536            // 256*256
#define HW4_ (HW_/4)          // 16384 float4 per plane
#define EPS_ 1e-12f

// ---- scratch (no allocations allowed) ----
__device__ float         g_a[B_ * C_];        // raw channel means
__device__ float         g_w[B_ * C_];        // a / max(||a||, eps)
__device__ unsigned int  g_hist[B_ * 256];    // per-batch histogram
__device__ unsigned char g_q[B_ * HW_];       // quantized cos map
__device__ float         g_lut[B_ * 256];     // equalized value / 255

// ------------------------------------------------------------------
// K1: mean over each (b,c) plane. 1024 blocks x 256 threads.
// ------------------------------------------------------------------
__global__ void __launch_bounds__(256) mean_kernel(const float* __restrict__ F) {
    int bc = blockIdx.x;                       // 0..1023
    const float4* p = reinterpret_cast<const float4*>(F) + (size_t)bc * HW4_;
    float s = 0.f;
    #pragma unroll 4
    for (int i = threadIdx.x; i < HW4_; i += 256) {
        float4 v = p[i];
        s += (v.x + v.y) + (v.z + v.w);
    }
    // warp reduce
    #pragma unroll
    for (int o = 16; o > 0; o >>= 1) s += __shfl_down_sync(0xffffffffu, s, o);
    __shared__ float sh[8];
    if ((threadIdx.x & 31) == 0) sh[threadIdx.x >> 5] = s;
    __syncthreads();
    if (threadIdx.x == 0) {
        float t = 0.f;
        #pragma unroll
        for (int i = 0; i < 8; i++) t += sh[i];
        g_a[bc] = t * (1.0f / (float)HW_);
    }
}

// ------------------------------------------------------------------
// K1b: normalize a per batch; zero histograms. 1 block x 1024 threads.
// ------------------------------------------------------------------
__global__ void norm_kernel() {
    __shared__ float ssum[B_];
    int t = threadIdx.x;                       // 0..1023 == b*64 + c
    if (t < B_) ssum[t] = 0.f;
    __syncthreads();
    float av = g_a[t];
    atomicAdd(&ssum[t >> 6], av * av);
    __syncthreads();
    float n = fmaxf(sqrtf(ssum[t >> 6]), EPS_);
    g_w[t] = av / n;
    for (int i = t; i < B_ * 256; i += 1024) g_hist[i] = 0u;
}

// ------------------------------------------------------------------
// K2: cos-sim per pixel, quantize, histogram.
// grid (HW4_/256, B_), 256 threads. Each thread: 4 pixels (float4/channel).
// Two independent accumulator chains (c and c+32) for MLP.
// ------------------------------------------------------------------
__global__ void __launch_bounds__(256) cos_hist_kernel(const float* __restrict__ F) {
    int b = blockIdx.y;
    __shared__ unsigned int sh[256];
    __shared__ float sw[C_];
    if (threadIdx.x < 256) sh[threadIdx.x] = 0u;
    if (threadIdx.x < C_)  sw[threadIdx.x] = g_w[b * C_ + threadIdx.x];
    __syncthreads();

    int hw4 = blockIdx.x * 256 + threadIdx.x;  // 0..16383
    const float4* base =
        reinterpret_cast<const float4*>(F) + (size_t)b * C_ * HW4_ + hw4;

    float4 dotA = make_float4(0.f, 0.f, 0.f, 0.f);
    float4 ssA  = make_float4(0.f, 0.f, 0.f, 0.f);
    float4 dotB = make_float4(0.f, 0.f, 0.f, 0.f);
    float4 ssB  = make_float4(0.f, 0.f, 0.f, 0.f);
    #pragma unroll 8
    for (int c = 0; c < C_ / 2; c++) {
        float4 v0 = base[(size_t)c * HW4_];
        float4 v1 = base[(size_t)(c + C_ / 2) * HW4_];
        float  w0 = sw[c];
        float  w1 = sw[c + C_ / 2];
        dotA.x += w0 * v0.x;  dotA.y += w0 * v0.y;
        dotA.z += w0 * v0.z;  dotA.w += w0 * v0.w;
        ssA.x  += v0.x * v0.x; ssA.y += v0.y * v0.y;
        ssA.z  += v0.z * v0.z; ssA.w += v0.w * v0.w;
        dotB.x += w1 * v1.x;  dotB.y += w1 * v1.y;
        dotB.z += w1 * v1.z;  dotB.w += w1 * v1.w;
        ssB.x  += v1.x * v1.x; ssB.y += v1.y * v1.y;
        ssB.z  += v1.z * v1.z; ssB.w += v1.w * v1.w;
    }
    float4 dot = make_float4(dotA.x + dotB.x, dotA.y + dotB.y,
                             dotA.z + dotB.z, dotA.w + dotB.w);
    float4 ss  = make_float4(ssA.x + ssB.x, ssA.y + ssB.y,
                             ssA.z + ssB.z, ssA.w + ssB.w);

    int q0 = ((int)((dot.x / fmaxf(sqrtf(ss.x), EPS_)) * 255.0f)) & 255;
    int q1 = ((int)((dot.y / fmaxf(sqrtf(ss.y), EPS_)) * 255.0f)) & 255;
    int q2 = ((int)((dot.z / fmaxf(sqrtf(ss.z), EPS_)) * 255.0f)) & 255;
    int q3 = ((int)((dot.w / fmaxf(sqrtf(ss.w), EPS_)) * 255.0f)) & 255;

    uchar4 qv = make_uchar4((unsigned char)q0, (unsigned char)q1,
                            (unsigned char)q2, (unsigned char)q3);
    *reinterpret_cast<uchar4*>(g_q + (size_t)b * HW_ + (size_t)hw4 * 4) = qv;

    atomicAdd(&sh[q0], 1u);
    atomicAdd(&sh[q1], 1u);
    atomicAdd(&sh[q2], 1u);
    atomicAdd(&sh[q3], 1u);
    __syncthreads();
    if (threadIdx.x < 256) {
        unsigned int v = sh[threadIdx.x];
        if (v) atomicAdd(&g_hist[b * 256 + threadIdx.x], v);
    }
}

// ------------------------------------------------------------------
// K3: histogram -> equalization LUT (pre-divided by 255). B_ blocks x 256.
// ------------------------------------------------------------------
__global__ void lut_kernel() {
    int b = blockIdx.x;
    int t = threadIdx.x;
    __shared__ float cdf[256];
    __shared__ float mn[256];

    float h = (float)g_hist[b * 256 + t];
    cdf[t] = h;
    __syncthreads();
    // Hillis-Steele inclusive scan
    #pragma unroll
    for (int off = 1; off < 256; off <<= 1) {
        float v = (t >= off) ? cdf[t - off] : 0.f;
        __syncthreads();
        cdf[t] += v;
        __syncthreads();
    }
    mn[t] = (h > 0.f) ? cdf[t] : ((float)HW_ + 1.0f);
    __syncthreads();
    #pragma unroll
    for (int off = 128; off > 0; off >>= 1) {
        if (t < off) mn[t] = fminf(mn[t], mn[t + off]);
        __syncthreads();
    }
    float cdf_min = mn[0];
    float denom = fmaxf((float)HW_ - cdf_min, 1.0f);
    float scale = 255.0f / denom;
    float lutv = rintf((cdf[t] - cdf_min) * scale);   // round-half-even == jnp.round
    lutv = fminf(fmaxf(lutv, 0.0f), 255.0f);
    g_lut[b * 256 + t] = lutv / 255.0f;
}

// ------------------------------------------------------------------
// K4: out = lut[b][q[b,hw]] * F. grid (C_*HW4_/256, B_), 256 threads.
// ------------------------------------------------------------------
__global__ void __launch_bounds__(256) apply_kernel(const float* __restrict__ F,
                                                    float* __restrict__ out) {
    int b = blockIdx.y;
    __shared__ float slut[256];
    slut[threadIdx.x] = g_lut[b * 256 + threadIdx.x];
    __syncthreads();

    size_t e4 = (size_t)blockIdx.x * 256 + threadIdx.x;   // float4 index within batch
    size_t gidx = (size_t)b * C_ * HW4_ + e4;
    int hw4 = (int)(e4 & (HW4_ - 1));                      // hw4 within plane

    float4 v = reinterpret_cast<const float4*>(F)[gidx];
    uchar4 qv = *reinterpret_cast<const uchar4*>(g_q + (size_t)b * HW_ + (size_t)hw4 * 4);

    float4 o;
    o.x = slut[qv.x] * v.x;
    o.y = slut[qv.y] * v.y;
    o.z = slut[qv.z] * v.z;
    o.w = slut[qv.w] * v.w;
    reinterpret_cast<float4*>(out)[gidx] = o;
}

// ------------------------------------------------------------------
extern "C" void kernel_launch(void* const* d_in, const int* in_sizes, int n_in,
                              void* d_out, int out_size) {
    const float* F = (const float*)d_in[0];
    float* out = (float*)d_out;

    mean_kernel<<<B_ * C_, 256>>>(F);
    norm_kernel<<<1, 1024>>>();
    {
        dim3 g(HW4_ / 256, B_);
        cos_hist_kernel<<<g, 256>>>(F);
    }
    lut_kernel<<<B_, 256>>>();
    {
        dim3 g((C_ * HW4_) / 256, B_);
        apply_kernel<<<g, 256>>>(F, out);
    }
}